// round 14
// baseline (speedup 1.0000x reference)
#include <cuda_runtime.h>

#define NQ   12
#define DIM  4096
#define NL   6
#define TPB  512

// padded smem slot to avoid bank conflicts in strided passes
#define SLOT(i) ((i) + ((i) >> 4))

struct Smem {
    float2 psi[2][DIM + (DIM >> 4)];                  // two padded states, ~68 KB
    float2 DphiHi[NL][64], DphiLo[NL][64];            // Pi Rz(phi) split tables
    float2 DomHi[NL][64],  DomLo[NL][64];             // Pi Rz(omega) split tables
    float2 PhiC[2][64], PloC[2][64];                  // per-state complex init tables
    unsigned short fwdHi[NL][64], fwdLo[NL][64];      // FORWARD CNOT-layer perm (GF2 split)
    float  ryc[NL][NQ], rys[NL][NQ];                  // Ry cos/sin
    float  phi05[NL][NQ], om05[NL][NQ];               // half-angles for diagonals
    float  Thi[64], Tlo[64];                          // signed-weight readout tables
    float  cw[2][NQ], sw[2][NQ], Wv[NQ];
    float  red[2][TPB / 32];
};

__device__ __forceinline__ float2 cmul(const float2 a, const float2 b) {
    float2 r;
    r.x = fmaf(a.x, b.x, -a.y * b.y);
    r.y = fmaf(a.x, b.y,  a.y * b.x);
    return r;
}

// Real Ry butterfly on register-pairing bit P (v has 8 entries, P in 0..2).
template <int P>
__device__ __forceinline__ void apply_ry8(float2 v[8], const float c, const float s) {
#pragma unroll
    for (int j0 = 0; j0 < 8; ++j0) {
        if (j0 & (1 << P)) continue;
        const int j1 = j0 | (1 << P);
        const float2 a = v[j0], b = v[j1];
        float2 n0, n1;
        n0.x = fmaf(c, a.x, -s * b.x);
        n0.y = fmaf(c, a.y, -s * b.y);
        n1.x = fmaf(s, a.x,  c * b.x);
        n1.y = fmaf(s, a.y,  c * b.y);
        v[j0] = n0; v[j1] = n1;
    }
}

// Real Ry butterfly across lanes: pairing on lane bit TB (intra-warp, no smem/sync).
// n = c*own + ks*other, ks = bit? +s : -s
template <int TB>
__device__ __forceinline__ void apply_ry_shfl8(float2 v[8], const float c, const float s,
                                               const int tid) {
    const float ks = ((tid >> TB) & 1) ? s : -s;
#pragma unroll
    for (int j = 0; j < 8; ++j) {
        const float ox = __shfl_xor_sync(0xFFFFFFFFu, v[j].x, 1 << TB);
        const float oy = __shfl_xor_sync(0xFFFFFFFFu, v[j].y, 1 << TB);
        v[j].x = fmaf(ks, ox, c * v[j].x);
        v[j].y = fmaf(ks, oy, c * v[j].y);
    }
}

__global__ void __launch_bounds__(TPB, 2)
quantum_kernel(const float* __restrict__ x,
               const float* __restrict__ weights,
               const float* __restrict__ Wlin,
               const float* __restrict__ bias_p,
               float* __restrict__ out)
{
    extern __shared__ unsigned char smem_raw[];
    Smem* sm = reinterpret_cast<Smem*>(smem_raw);

    const int tid = threadIdx.x;          // 9 bits
    const int bidx = blockIdx.x;          // this CTA handles batches 2*bidx and 2*bidx+1

    // ---------- Phase 1: embedding trig (both states), Ry constants, half-angles, FWD CNOT tables ----------
    if (tid < 2 * NQ) {
        const int s = tid / NQ, w = tid % NQ;
        float h = 0.5f * x[(2 * bidx + s) * NQ + w];
        sincosf(h, &sm->sw[s][w], &sm->cw[s][w]);
        if (s == 0) sm->Wv[w] = Wlin[w];
    }
    if (tid < NL * NQ) {
        const int l = tid / NQ, w = tid % NQ;
        const float* wp = weights + (l * NQ + w) * 3;
        float st, ct; sincosf(0.5f * wp[1], &st, &ct);
        sm->ryc[l][w] = ct; sm->rys[l][w] = st;
        sm->phi05[l][w] = 0.5f * wp[0];
        sm->om05[l][w]  = 0.5f * wp[2];
    }
    // FORWARD permutation: apply CNOT(w, (w+r)%NQ) for w = 0..11 ascending, tracking the live index.
    for (int idx = tid; idx < NL * 128; idx += TPB) {
        const int l = idx >> 7, k = idx & 127;
        const int r = l % (NQ - 1) + 1;
        unsigned v = (k < 64) ? (unsigned)k : ((unsigned)(k - 64) << 6);
        for (int w = 0; w < NQ; ++w) {
            const int t = (w + r) % NQ;
            v ^= ((v >> (NQ - 1 - w)) & 1u) << (NQ - 1 - t);
        }
        if (k < 64) sm->fwdLo[l][k] = (unsigned short)v;
        else        sm->fwdHi[l][k - 64] = (unsigned short)v;
    }
    __syncthreads();

    // ---------- Phase 2: diagonal phase tables. Rz(a) = diag(e^{-ia/2}, e^{+ia/2}) ----------
    for (int idx = tid; idx < NL * 4 * 64; idx += TPB) {
        const int l = idx >> 8;
        const int which = (idx >> 6) & 3;       // 0 phiHi, 1 phiLo, 2 omHi, 3 omLo
        const int e = idx & 63;
        const float* ang = (which < 2) ? &sm->phi05[l][0] : &sm->om05[l][0];
        const int base = (which & 1) ? 6 : 0;   // lo half covers wires 6..11
        float a = 0.f;
#pragma unroll
        for (int w = 0; w < 6; ++w) {
            const float aw = ang[base + w];
            a += ((e >> (5 - w)) & 1) ? aw : -aw;
        }
        float sn, cs; sincosf(a, &sn, &cs);
        const float2 ph = make_float2(cs, sn);
        if      (which == 0) sm->DphiHi[l][e] = ph;
        else if (which == 1) sm->DphiLo[l][e] = ph;
        else if (which == 2) sm->DomHi[l][e]  = ph;
        else                 sm->DomLo[l][e]  = ph;
    }
    __syncthreads();

    // ---------- Phase 3: per-state init tables (embedding * layer-0 phi diag), readout tables ----------
    if (tid < 128) {
        const int s = tid >> 6, j = tid & 63;
        float ph = 1.f, pl = 1.f, th = 0.f, tl = 0.f;
#pragma unroll
        for (int w = 0; w < 6; ++w) {
            const int b = (j >> (5 - w)) & 1;
            ph *= b ? sm->sw[s][w] : sm->cw[s][w];
            pl *= b ? sm->sw[s][6 + w] : sm->cw[s][6 + w];
            th += b ? -sm->Wv[w] : sm->Wv[w];
            tl += b ? -sm->Wv[6 + w] : sm->Wv[6 + w];
        }
        sm->PhiC[s][j] = make_float2(ph * sm->DphiHi[0][j].x, ph * sm->DphiHi[0][j].y);
        sm->PloC[s][j] = make_float2(pl * sm->DphiLo[0][j].x, pl * sm->DphiLo[0][j].y);
        if (s == 0) { sm->Thi[j] = th; sm->Tlo[j] = tl; }
    }
    __syncthreads();

    // ---------- Circuit ----------
    // Pass A layout: amp = (tid<<3)|j    -> wires 9-11 in regs (j), wires 4-8 on lane bits 4..0 (shfl)
    // Pass C layout: amp = (j<<9)|(lane4<<8)|((tid>>5)<<4)|(tid&15)
    //                                    -> wires 0-2 in regs (j), wire 3 on lane bit 4 (shfl)
    float2 v[8];
    const int cb = ((tid >> 5) << 4) | (tid & 15);        // pass-C base: amp bits 0-7 sans bit 8
    const int cLo6 = cb & 63;                             // pass-C low-6 amp bits (const per thread)
    const int cHiBase = (((tid >> 4) & 1) << 2) | ((tid >> 7) & 3); // amp bits 8..6 sans j
#pragma unroll 1
    for (int l = 0; l < NL; ++l) {
        // ---- Pass A: thread-private slots + intra-warp shfl; no intra-pass hazard
#pragma unroll 1
        for (int s = 0; s < 2; ++s) {
            if (l == 0) {
                const float2 ph = sm->PhiC[s][tid >> 3];
#pragma unroll
                for (int j = 0; j < 8; ++j)
                    v[j] = cmul(ph, sm->PloC[s][((tid & 7) << 3) | j]);
            } else {
                const float2 dh = sm->DphiHi[l][tid >> 3];
#pragma unroll
                for (int j = 0; j < 8; ++j) {
                    const float2 d = cmul(dh, sm->DphiLo[l][((tid & 7) << 3) | j]);
                    v[j] = cmul(d, sm->psi[s][SLOT((tid << 3) | j)]);
                }
            }
            apply_ry8<2>(v, sm->ryc[l][9],  sm->rys[l][9]);    // wire 9  -> amp bit 2
            apply_ry8<1>(v, sm->ryc[l][10], sm->rys[l][10]);   // wire 10 -> amp bit 1
            apply_ry8<0>(v, sm->ryc[l][11], sm->rys[l][11]);   // wire 11 -> amp bit 0
            apply_ry_shfl8<4>(v, sm->ryc[l][4], sm->rys[l][4], tid);  // wire 4 -> amp bit 7 -> lane bit 4
            apply_ry_shfl8<3>(v, sm->ryc[l][5], sm->rys[l][5], tid);  // wire 5 -> lane bit 3
            apply_ry_shfl8<2>(v, sm->ryc[l][6], sm->rys[l][6], tid);  // wire 6 -> lane bit 2
            apply_ry_shfl8<1>(v, sm->ryc[l][7], sm->rys[l][7], tid);  // wire 7 -> lane bit 1
            apply_ry_shfl8<0>(v, sm->ryc[l][8], sm->rys[l][8], tid);  // wire 8 -> lane bit 0
#pragma unroll
            for (int j = 0; j < 8; ++j) sm->psi[s][SLOT((tid << 3) | j)] = v[j];
        }
        __syncthreads();

        // ---- Pass C: wires 0-2 in regs, wire 3 via shfl(lane bit 4); barrier-protected perm scatter
#pragma unroll 1
        for (int s = 0; s < 2; ++s) {
#pragma unroll
            for (int j = 0; j < 8; ++j)
                v[j] = sm->psi[s][SLOT((j << 9) | (((tid >> 4) & 1) << 8) | cb)];
            apply_ry8<2>(v, sm->ryc[l][0], sm->rys[l][0]);     // wire 0 -> amp bit 11 -> j bit 2
            apply_ry8<1>(v, sm->ryc[l][1], sm->rys[l][1]);     // wire 1 -> j bit 1
            apply_ry8<0>(v, sm->ryc[l][2], sm->rys[l][2]);     // wire 2 -> j bit 0
            apply_ry_shfl8<4>(v, sm->ryc[l][3], sm->rys[l][3], tid);  // wire 3 -> amp bit 8 -> lane bit 4
            __syncthreads();   // all loads of psi[s] complete before any scatter into psi[s]
            const unsigned short fl = sm->fwdLo[l][cLo6];
            if (l < NL - 1) {
                const float2 dlo = sm->DomLo[l][cLo6];
#pragma unroll
                for (int j = 0; j < 8; ++j) {
                    const int hi6 = (j << 3) | cHiBase;
                    const int dst = sm->fwdHi[l][hi6] ^ fl;
                    const float2 d = cmul(sm->DomHi[l][hi6], dlo);
                    sm->psi[s][SLOT(dst)] = cmul(d, v[j]);
                }
            } else {
                // final layer: omega diagonal is a pure phase before |psi|^2 -> dropped
#pragma unroll
                for (int j = 0; j < 8; ++j) {
                    const int dst = sm->fwdHi[l][(j << 3) | cHiBase] ^ fl;
                    sm->psi[s][SLOT(dst)] = v[j];
                }
            }
        }
        __syncthreads();
    }

    // ---------- Readout: state already in final order; probs * signed-weight table ----------
#pragma unroll 1
    for (int s = 0; s < 2; ++s) {
        const float th = sm->Thi[tid >> 3];
        float acc = 0.f;
#pragma unroll
        for (int j = 0; j < 8; ++j) {
            const float2 a = sm->psi[s][SLOT((tid << 3) | j)];
            acc = fmaf(fmaf(a.x, a.x, a.y * a.y),
                       th + sm->Tlo[((tid & 7) << 3) | j], acc);
        }
#pragma unroll
        for (int o = 16; o; o >>= 1) acc += __shfl_xor_sync(0xFFFFFFFFu, acc, o);
        if ((tid & 31) == 0) sm->red[s][tid >> 5] = acc;
    }
    __syncthreads();
    if (tid < 2) {
        float ssum = 0.f;
#pragma unroll
        for (int k = 0; k < TPB / 32; ++k) ssum += sm->red[tid][k];
        out[2 * bidx + tid] = ssum + bias_p[0];
    }
}

extern "C" void kernel_launch(void* const* d_in, const int* in_sizes, int n_in,
                              void* d_out, int out_size)
{
    const float* x       = (const float*)d_in[0];
    const float* weights = (const float*)d_in[1];
    const float* W       = (const float*)d_in[2];
    const float* b       = (const float*)d_in[3];
    float* out = (float*)d_out;

    cudaFuncSetAttribute(quantum_kernel,
                         cudaFuncAttributeMaxDynamicSharedMemorySize,
                         (int)sizeof(Smem));
    quantum_kernel<<<256, TPB, sizeof(Smem)>>>(x, weights, W, b, out);
}

// round 17
// speedup vs baseline: 1.0880x; 1.0880x over previous
#include <cuda_runtime.h>

#define NQ   12
#define DIM  4096
#define NL   6
#define TPB  256

// padding keeps 16B alignment for float4 ops: slot = i + 2*(i>>4)
#define SLOT2(i) ((i) + (((i) >> 4) << 1))
#define PSIN (DIM + ((DIM >> 4) << 1))

struct Smem {
    // float2/float4-aligned arrays first (all sizes multiples of 16B)
    float2 psi[2][PSIN];                              // two padded states, ~72 KB
    float2 DphiHi[NL][64], DphiLo[NL][64];            // Pi Rz(phi) split tables
    float2 DomHi[NL][64],  DomLo[NL][64];             // Pi Rz(omega) split tables
    float2 PhiC[2][64], PloC[2][64];                  // per-state complex init tables
    unsigned short fwdHi[NL][64], fwdLo[NL][64];      // FORWARD CNOT-layer perm (GF2 split)
    float  ryc[NL][NQ], rys[NL][NQ];                  // Ry cos/sin
    float  phi05[NL][NQ], om05[NL][NQ];               // half-angles for diagonals
    float  Thi[64], Tlo[64];                          // signed-weight readout tables
    float  cw[2][NQ], sw[2][NQ], Wv[NQ];
    float  red[2][TPB / 32];
};

__device__ __forceinline__ float2 cmul(const float2 a, const float2 b) {
    float2 r;
    r.x = fmaf(a.x, b.x, -a.y * b.y);
    r.y = fmaf(a.x, b.y,  a.y * b.x);
    return r;
}

// Real Ry butterfly on register-pairing bit P of a 16-entry v.
template <int P>
__device__ __forceinline__ void apply_ry(float2 v[16], const float c, const float s) {
#pragma unroll
    for (int j0 = 0; j0 < 16; ++j0) {
        if (j0 & (1 << P)) continue;
        const int j1 = j0 | (1 << P);
        const float2 a = v[j0], b = v[j1];
        float2 n0, n1;
        n0.x = fmaf(c, a.x, -s * b.x);
        n0.y = fmaf(c, a.y, -s * b.y);
        n1.x = fmaf(s, a.x,  c * b.x);
        n1.y = fmaf(s, a.y,  c * b.y);
        v[j0] = n0; v[j1] = n1;
    }
}

// Real Ry butterfly across lanes on lane bit TB (intra-warp, no smem/sync).
template <int TB>
__device__ __forceinline__ void apply_ry_shfl(float2 v[16], const float c, const float s,
                                              const int tid) {
    const float ks = ((tid >> TB) & 1) ? s : -s;
#pragma unroll
    for (int j = 0; j < 16; ++j) {
        const float ox = __shfl_xor_sync(0xFFFFFFFFu, v[j].x, 1 << TB);
        const float oy = __shfl_xor_sync(0xFFFFFFFFu, v[j].y, 1 << TB);
        v[j].x = fmaf(ks, ox, c * v[j].x);
        v[j].y = fmaf(ks, oy, c * v[j].y);
    }
}

__global__ void __launch_bounds__(TPB, 2)
quantum_kernel(const float* __restrict__ x,
               const float* __restrict__ weights,
               const float* __restrict__ Wlin,
               const float* __restrict__ bias_p,
               float* __restrict__ out)
{
    extern __shared__ unsigned char smem_raw[];
    Smem* sm = reinterpret_cast<Smem*>(smem_raw);

    const int tid = threadIdx.x;
    const int bidx = blockIdx.x;          // batches 2*bidx and 2*bidx+1

    // ---------- Phase 1: embedding trig, Ry constants, half-angles, FWD CNOT tables ----------
    if (tid < 2 * NQ) {
        const int s = tid / NQ, w = tid % NQ;
        float h = 0.5f * x[(2 * bidx + s) * NQ + w];
        sincosf(h, &sm->sw[s][w], &sm->cw[s][w]);
        if (s == 0) sm->Wv[w] = Wlin[w];
    }
    if (tid < NL * NQ) {
        const int l = tid / NQ, w = tid % NQ;
        const float* wp = weights + (l * NQ + w) * 3;
        float st, ct; sincosf(0.5f * wp[1], &st, &ct);
        sm->ryc[l][w] = ct; sm->rys[l][w] = st;
        sm->phi05[l][w] = 0.5f * wp[0];
        sm->om05[l][w]  = 0.5f * wp[2];
    }
    // FORWARD permutation: apply CNOT(w, (w+r)%NQ) for w = 0..11 ascending.
    for (int idx = tid; idx < NL * 128; idx += TPB) {
        const int l = idx >> 7, k = idx & 127;
        const int r = l % (NQ - 1) + 1;
        unsigned v = (k < 64) ? (unsigned)k : ((unsigned)(k - 64) << 6);
        for (int w = 0; w < NQ; ++w) {
            const int t = (w + r) % NQ;
            v ^= ((v >> (NQ - 1 - w)) & 1u) << (NQ - 1 - t);
        }
        if (k < 64) sm->fwdLo[l][k] = (unsigned short)v;
        else        sm->fwdHi[l][k - 64] = (unsigned short)v;
    }
    __syncthreads();

    // ---------- Phase 2: diagonal phase tables. Rz(a) = diag(e^{-ia/2}, e^{+ia/2}) ----------
    for (int idx = tid; idx < NL * 4 * 64; idx += TPB) {
        const int l = idx >> 8;
        const int which = (idx >> 6) & 3;       // 0 phiHi, 1 phiLo, 2 omHi, 3 omLo
        const int e = idx & 63;
        const float* ang = (which < 2) ? &sm->phi05[l][0] : &sm->om05[l][0];
        const int base = (which & 1) ? 6 : 0;   // lo half covers wires 6..11
        float a = 0.f;
#pragma unroll
        for (int w = 0; w < 6; ++w) {
            const float aw = ang[base + w];
            a += ((e >> (5 - w)) & 1) ? aw : -aw;
        }
        float sn, cs; sincosf(a, &sn, &cs);
        const float2 ph = make_float2(cs, sn);
        if      (which == 0) sm->DphiHi[l][e] = ph;
        else if (which == 1) sm->DphiLo[l][e] = ph;
        else if (which == 2) sm->DomHi[l][e]  = ph;
        else                 sm->DomLo[l][e]  = ph;
    }
    __syncthreads();

    // ---------- Phase 3: per-state init tables (embedding * layer-0 phi diag), readout tables ----------
    if (tid < 128) {
        const int s = tid >> 6, j = tid & 63;
        float ph = 1.f, pl = 1.f, th = 0.f, tl = 0.f;
#pragma unroll
        for (int w = 0; w < 6; ++w) {
            const int b = (j >> (5 - w)) & 1;
            ph *= b ? sm->sw[s][w] : sm->cw[s][w];
            pl *= b ? sm->sw[s][6 + w] : sm->cw[s][6 + w];
            th += b ? -sm->Wv[w] : sm->Wv[w];
            tl += b ? -sm->Wv[6 + w] : sm->Wv[6 + w];
        }
        sm->PhiC[s][j] = make_float2(ph * sm->DphiHi[0][j].x, ph * sm->DphiHi[0][j].y);
        sm->PloC[s][j] = make_float2(pl * sm->DphiLo[0][j].x, pl * sm->DphiLo[0][j].y);
        if (s == 0) { sm->Thi[j] = th; sm->Tlo[j] = tl; }
    }
    __syncthreads();

    // ---------- Circuit ----------
    // Pass A layout: amp = (tid<<4)|j        (slot = 18*tid + j, float4-pair friendly)
    //   wires 8-11 on j bits 3-0 (regs), wires 4-7 on tid/lane bits 3-0 (shfl)
    // Pass C layout: amp = (jj<<9)|(lane4<<8)|(warp<<5)|(laneLow<<1)|p  -> pairs contiguous
    //   wires 0-2 on jj bits (v-index bits 3-1), wire 3 on lane bit 4 (shfl)
    float2 v[16];
    const int l4  = (tid >> 4) & 1;
    const int wrp = tid >> 5;
    const int lL  = tid & 15;
    const int ampBase = (l4 << 8) | (wrp << 5) | (lL << 1);
    const int baseLo  = ((wrp & 1) << 5) | (lL << 1);       // amp bits 5-0 sans p
    const int hiBase  = (l4 << 2) | (wrp >> 1);             // amp bits 8-6 sans jj
    float acc[2] = {0.f, 0.f};

#pragma unroll 1
    for (int l = 0; l < NL; ++l) {
        // ---- Pass A: thread-private slots + intra-warp shfl; no intra-pass hazard
#pragma unroll 1
        for (int s = 0; s < 2; ++s) {
            if (l == 0) {
                const float2 ph = sm->PhiC[s][tid >> 2];
                const float4* plo4 = reinterpret_cast<const float4*>(&sm->PloC[s][(tid & 3) << 4]);
#pragma unroll
                for (int k = 0; k < 8; ++k) {
                    const float4 t = plo4[k];
                    v[2 * k]     = cmul(ph, make_float2(t.x, t.y));
                    v[2 * k + 1] = cmul(ph, make_float2(t.z, t.w));
                }
            } else {
                const float2 dh = sm->DphiHi[l][tid >> 2];
                const float4* dlo4 = reinterpret_cast<const float4*>(&sm->DphiLo[l][(tid & 3) << 4]);
                const float4* ps4 = reinterpret_cast<const float4*>(&sm->psi[s][18 * tid]);
#pragma unroll
                for (int k = 0; k < 8; ++k) {
                    const float4 dd = dlo4[k];
                    const float4 pv = ps4[k];
                    v[2 * k]     = cmul(cmul(dh, make_float2(dd.x, dd.y)), make_float2(pv.x, pv.y));
                    v[2 * k + 1] = cmul(cmul(dh, make_float2(dd.z, dd.w)), make_float2(pv.z, pv.w));
                }
            }
            apply_ry<3>(v, sm->ryc[l][8],  sm->rys[l][8]);    // wire 8  -> amp bit 3
            apply_ry<2>(v, sm->ryc[l][9],  sm->rys[l][9]);    // wire 9  -> amp bit 2
            apply_ry<1>(v, sm->ryc[l][10], sm->rys[l][10]);   // wire 10 -> amp bit 1
            apply_ry<0>(v, sm->ryc[l][11], sm->rys[l][11]);   // wire 11 -> amp bit 0
            apply_ry_shfl<3>(v, sm->ryc[l][4], sm->rys[l][4], tid);  // wire 4 -> amp bit 7
            apply_ry_shfl<2>(v, sm->ryc[l][5], sm->rys[l][5], tid);  // wire 5 -> amp bit 6
            apply_ry_shfl<1>(v, sm->ryc[l][6], sm->rys[l][6], tid);  // wire 6 -> amp bit 5
            apply_ry_shfl<0>(v, sm->ryc[l][7], sm->rys[l][7], tid);  // wire 7 -> amp bit 4
            {
                float4* ps4w = reinterpret_cast<float4*>(&sm->psi[s][18 * tid]);
#pragma unroll
                for (int k = 0; k < 8; ++k)
                    ps4w[k] = make_float4(v[2 * k].x, v[2 * k].y, v[2 * k + 1].x, v[2 * k + 1].y);
            }
        }
        __syncthreads();

        // ---- Pass C: wires 0-2 in regs (jj), wire 3 via shfl(lane bit 4)
        if (l < NL - 1) {
#pragma unroll 1
            for (int s = 0; s < 2; ++s) {
#pragma unroll
                for (int jj = 0; jj < 8; ++jj) {
                    const int amp0 = (jj << 9) | ampBase;
                    const float4 pv = *reinterpret_cast<const float4*>(&sm->psi[s][SLOT2(amp0)]);
                    v[2 * jj]     = make_float2(pv.x, pv.y);
                    v[2 * jj + 1] = make_float2(pv.z, pv.w);
                }
                apply_ry<3>(v, sm->ryc[l][0], sm->rys[l][0]);     // wire 0 -> amp bit 11 -> v bit 3
                apply_ry<2>(v, sm->ryc[l][1], sm->rys[l][1]);     // wire 1 -> v bit 2
                apply_ry<1>(v, sm->ryc[l][2], sm->rys[l][2]);     // wire 2 -> v bit 1
                apply_ry_shfl<4>(v, sm->ryc[l][3], sm->rys[l][3], tid);  // wire 3 -> amp bit 8
                __syncthreads();   // all loads of psi[s] complete before any scatter into psi[s]
                const unsigned short fl0 = sm->fwdLo[l][baseLo];
                const unsigned short fl1 = sm->fwdLo[l][baseLo | 1];
                const float2 dlo0 = sm->DomLo[l][baseLo];
                const float2 dlo1 = sm->DomLo[l][baseLo | 1];
#pragma unroll
                for (int jj = 0; jj < 8; ++jj) {
                    const int hi6 = (jj << 3) | hiBase;
                    const unsigned short fh = sm->fwdHi[l][hi6];
                    const float2 dhv = sm->DomHi[l][hi6];
                    sm->psi[s][SLOT2(fh ^ fl0)] = cmul(cmul(dhv, dlo0), v[2 * jj]);
                    sm->psi[s][SLOT2(fh ^ fl1)] = cmul(cmul(dhv, dlo1), v[2 * jj + 1]);
                }
            }
            __syncthreads();
        } else {
            // ---- Final layer: fuse readout into pass C — no scatter, no reload, no barrier.
            //      omega diagonal is a pure phase before |psi|^2 -> dropped.
#pragma unroll 1
            for (int s = 0; s < 2; ++s) {
#pragma unroll
                for (int jj = 0; jj < 8; ++jj) {
                    const int amp0 = (jj << 9) | ampBase;
                    const float4 pv = *reinterpret_cast<const float4*>(&sm->psi[s][SLOT2(amp0)]);
                    v[2 * jj]     = make_float2(pv.x, pv.y);
                    v[2 * jj + 1] = make_float2(pv.z, pv.w);
                }
                apply_ry<3>(v, sm->ryc[l][0], sm->rys[l][0]);
                apply_ry<2>(v, sm->ryc[l][1], sm->rys[l][1]);
                apply_ry<1>(v, sm->ryc[l][2], sm->rys[l][2]);
                apply_ry_shfl<4>(v, sm->ryc[l][3], sm->rys[l][3], tid);
                const unsigned short fl0 = sm->fwdLo[l][baseLo];
                const unsigned short fl1 = sm->fwdLo[l][baseLo | 1];
                float a = 0.f;
#pragma unroll
                for (int jj = 0; jj < 8; ++jj) {
                    const int hi6 = (jj << 3) | hiBase;
                    const unsigned short fh = sm->fwdHi[l][hi6];
                    const int d0 = fh ^ fl0, d1 = fh ^ fl1;
                    const float2 a0 = v[2 * jj], a1 = v[2 * jj + 1];
                    a = fmaf(fmaf(a0.x, a0.x, a0.y * a0.y),
                             sm->Thi[d0 >> 6] + sm->Tlo[d0 & 63], a);
                    a = fmaf(fmaf(a1.x, a1.x, a1.y * a1.y),
                             sm->Thi[d1 >> 6] + sm->Tlo[d1 & 63], a);
                }
                acc[s] = a;
            }
        }
    }

    // ---------- Block reduction of both states' accumulators ----------
#pragma unroll
    for (int s = 0; s < 2; ++s) {
        float a = acc[s];
#pragma unroll
        for (int o = 16; o; o >>= 1) a += __shfl_xor_sync(0xFFFFFFFFu, a, o);
        if ((tid & 31) == 0) sm->red[s][tid >> 5] = a;
    }
    __syncthreads();
    if (tid < 2) {
        float ssum = 0.f;
#pragma unroll
        for (int k = 0; k < TPB / 32; ++k) ssum += sm->red[tid][k];
        out[2 * bidx + tid] = ssum + bias_p[0];
    }
}

extern "C" void kernel_launch(void* const* d_in, const int* in_sizes, int n_in,
                              void* d_out, int out_size)
{
    const float* x       = (const float*)d_in[0];
    const float* weights = (const float*)d_in[1];
    const float* W       = (const float*)d_in[2];
    const float* b       = (const float*)d_in[3];
    float* out = (float*)d_out;

    cudaFuncSetAttribute(quantum_kernel,
                         cudaFuncAttributeMaxDynamicSharedMemorySize,
                         (int)sizeof(Smem));
    quantum_kernel<<<256, TPB, sizeof(Smem)>>>(x, weights, W, b, out);
}